// round 10
// baseline (speedup 1.0000x reference)
#include <cuda_runtime.h>
#include <math.h>

#define N_ADDR 150000
#define N_TX   200000
#define HID    32
#define E_TA   1000000
#define E_AA   500000
#define E_AT   1000000
#define E_TOT  2500000
#define NDST   500000      // concatenated dst space: [ta addr | aa addr | at tx]
#define SLOPE  0.2f
#define TB     256
#define SCAN_T 1024

// ---------------------------------------------------------------------------
// Scratch (device global — no runtime allocation)
// ---------------------------------------------------------------------------
struct __align__(128) Scratch {
    float ha [N_ADDR * HID];
    float ht [N_TX   * HID];
    float otx[N_TX   * HID];
    float oa1[N_ADDR * HID];
    float oa2[N_ADDR * HID];
    float as_at[N_ADDR * 4];
    float ad_at[N_TX   * 4];
    float as_ta[N_TX   * 4];
    float ad_ta[N_ADDR * 4];
    float as_aa[N_ADDR * 4];
    float ad_aa[N_ADDR * 4];
    float sem_parts[1024 * 64];
    float attn[2];
    int cnt[NDST];
    int rs [NDST + 1];
    int rs_cur[NDST];
    int col[E_TOT];
    int bsums[512];
};
__device__ Scratch g_scr;

__device__ __forceinline__ float leaky(float v) { return v >= 0.f ? v : SLOPE * v; }
__device__ __forceinline__ float tanh_approx(float x) {
    float r; asm("tanh.approx.f32 %0, %1;" : "=f"(r) : "f"(x)); return r;
}

// ---------------------------------------------------------------------------
// CSR build — concatenated over all 3 relations.
// edge order: [ta (1M) | aa (0.5M) | at (1M)]
// dst space:  [ta addr (150K) | aa addr (150K) | at tx (200K)]
// ---------------------------------------------------------------------------
__global__ void hist_fused(const int* __restrict__ ta_d, const int* __restrict__ aa_d,
                           const int* __restrict__ at_d, int* __restrict__ cnt)
{
    int e = blockIdx.x * blockDim.x + threadIdx.x;
    if (e >= E_TOT) return;
    int g;
    if (e < E_TA)             g = ta_d[e];
    else if (e < E_TA + E_AA) g = N_ADDR + aa_d[e - E_TA];
    else                      g = 2 * N_ADDR + at_d[e - E_TA - E_AA];
    atomicAdd(&cnt[g], 1);
}

// block-local exclusive scan + block sums
__global__ void scan_local(const int* __restrict__ cnt, int* __restrict__ rs,
                           int* __restrict__ bsums, int n)
{
    __shared__ int sd[SCAN_T];
    int tid = threadIdx.x;
    int i = blockIdx.x * SCAN_T + tid;
    int v = (i < n) ? cnt[i] : 0;
    sd[tid] = v;
    __syncthreads();
#pragma unroll
    for (int off = 1; off < SCAN_T; off <<= 1) {
        int t = (tid >= off) ? sd[tid - off] : 0;
        __syncthreads();
        sd[tid] += t;
        __syncthreads();
    }
    if (i < n) rs[i] = sd[tid] - v;
    if (tid == SCAN_T - 1) bsums[blockIdx.x] = sd[tid];
}

// add cross-block offsets; seed rs_cur; write sentinel
__global__ void scan_offset(int* __restrict__ rs, int* __restrict__ rs_cur,
                            const int* __restrict__ bsums, int n, int etot)
{
    __shared__ int sb[SCAN_T];
    int tid = threadIdx.x;
    int bid = blockIdx.x;
    int acc = 0;
    for (int j = tid; j < bid; j += SCAN_T) acc += bsums[j];
    sb[tid] = acc;
    __syncthreads();
#pragma unroll
    for (int off = SCAN_T / 2; off > 0; off >>= 1) {
        if (tid < off) sb[tid] += sb[tid + off];
        __syncthreads();
    }
    int offset = sb[0];
    int i = bid * SCAN_T + tid;
    if (i < n) {
        int r = rs[i] + offset;
        rs[i] = r;
        rs_cur[i] = r;
    }
    if (bid == 0 && tid == 0) rs[n] = etot;
}

__global__ void fill_fused(const int* __restrict__ ta_s, const int* __restrict__ ta_d,
                           const int* __restrict__ aa_s, const int* __restrict__ aa_d,
                           const int* __restrict__ at_s, const int* __restrict__ at_d,
                           int* __restrict__ rs_cur, int* __restrict__ col)
{
    int e = blockIdx.x * blockDim.x + threadIdx.x;
    if (e >= E_TOT) return;
    int g, s;
    if (e < E_TA)              { g = ta_d[e];                          s = ta_s[e]; }
    else if (e < E_TA + E_AA)  { g = N_ADDR + aa_d[e - E_TA];          s = aa_s[e - E_TA]; }
    else                       { g = 2*N_ADDR + at_d[e - E_TA - E_AA]; s = at_s[e - E_TA - E_AA]; }
    int pos = atomicAdd(&rs_cur[g], 1);
    col[pos] = s;
}

// ---------------------------------------------------------------------------
// Fused projection for both node types; L2/L3 addr path consumes the semantic
// combine on the fly. Blocks [0,nba) -> addr; [nba, nba+nbt) -> tx.
// ---------------------------------------------------------------------------
__global__ void proj_fused(int layer1, int nba_blocks,
                           const float* __restrict__ xa,
                           const float* __restrict__ xt,
                           const float* __restrict__ o1, const float* __restrict__ o2,
                           const float* __restrict__ attn,
                           const float* __restrict__ Wa, const float* __restrict__ ba,
                           const float* __restrict__ Wt, const float* __restrict__ bt,
                           float* __restrict__ ha, float* __restrict__ ht,
                           const float* __restrict__ attS, const float* __restrict__ attD,
                           float* __restrict__ as_at, float* __restrict__ ad_ta,
                           float* __restrict__ as_aa, float* __restrict__ ad_aa,
                           float* __restrict__ ad_at, float* __restrict__ as_ta)
{
    __shared__ float sW[64 * HID];
    __shared__ float sb[HID];
    __shared__ float satt[4][HID];
    int tid = threadIdx.x;
    bool is_addr = (blockIdx.x < (unsigned)nba_blocks);
    const float* W = is_addr ? Wa : Wt;
    const float* b = is_addr ? ba : bt;
    int Fin = layer1 ? 64 : 32;
    for (int i = tid; i < Fin * HID; i += blockDim.x) sW[i] = W[i];
    if (tid < HID) {
        sb[tid] = b[tid];
        if (is_addr) {
            satt[0][tid] = attS[tid];            // att_src[at]
            satt[1][tid] = attD[32 + tid];       // att_dst[ta]
            satt[2][tid] = attS[64 + tid];       // att_src[aa]
            satt[3][tid] = attD[64 + tid];       // att_dst[aa]
        } else {
            satt[0][tid] = attD[tid];            // att_dst[at]
            satt[1][tid] = attS[32 + tid];       // att_src[ta]
            satt[2][tid] = 0.f;
            satt[3][tid] = 0.f;
        }
    }
    __syncthreads();

    int blk = is_addr ? blockIdx.x : (blockIdx.x - nba_blocks);
    int N   = is_addr ? N_ADDR : N_TX;
    int n   = blk * blockDim.x + tid;
    if (n >= N) return;

    float acc[HID];
#pragma unroll
    for (int c = 0; c < HID; c++) acc[c] = sb[c];

    if (is_addr && !layer1) {
        float a0 = attn[0], a1 = attn[1];
        const float4* r1 = reinterpret_cast<const float4*>(o1 + (size_t)n * HID);
        const float4* r2 = reinterpret_cast<const float4*>(o2 + (size_t)n * HID);
#pragma unroll
        for (int k4 = 0; k4 < 8; k4++) {
            float4 u1 = r1[k4], u2 = r2[k4];
            float x0 = a0 * fmaxf(u1.x, 0.f) + a1 * fmaxf(u2.x, 0.f);
            float x1 = a0 * fmaxf(u1.y, 0.f) + a1 * fmaxf(u2.y, 0.f);
            float x2 = a0 * fmaxf(u1.z, 0.f) + a1 * fmaxf(u2.z, 0.f);
            float x3 = a0 * fmaxf(u1.w, 0.f) + a1 * fmaxf(u2.w, 0.f);
#pragma unroll
            for (int c = 0; c < HID; c++) {
                acc[c] = fmaf(x0, sW[(k4*4+0)*HID + c], acc[c]);
                acc[c] = fmaf(x1, sW[(k4*4+1)*HID + c], acc[c]);
                acc[c] = fmaf(x2, sW[(k4*4+2)*HID + c], acc[c]);
                acc[c] = fmaf(x3, sW[(k4*4+3)*HID + c], acc[c]);
            }
        }
    } else {
        const float* xr = is_addr ? (xa + (size_t)n * Fin) : (xt + (size_t)n * Fin);
        const float4* xv4 = reinterpret_cast<const float4*>(xr);
        int nk4 = Fin / 4;
        bool do_relu = (!layer1) && !is_addr;
#pragma unroll 4
        for (int k4 = 0; k4 < nk4; k4++) {
            float4 xv = xv4[k4];
            float x0 = do_relu ? fmaxf(xv.x, 0.f) : xv.x;
            float x1 = do_relu ? fmaxf(xv.y, 0.f) : xv.y;
            float x2 = do_relu ? fmaxf(xv.z, 0.f) : xv.z;
            float x3 = do_relu ? fmaxf(xv.w, 0.f) : xv.w;
#pragma unroll
            for (int c = 0; c < HID; c++) {
                acc[c] = fmaf(x0, sW[(k4*4+0)*HID + c], acc[c]);
                acc[c] = fmaf(x1, sW[(k4*4+1)*HID + c], acc[c]);
                acc[c] = fmaf(x2, sW[(k4*4+2)*HID + c], acc[c]);
                acc[c] = fmaf(x3, sW[(k4*4+3)*HID + c], acc[c]);
            }
        }
    }

    float* h = is_addr ? ha : ht;
    float4* hv = reinterpret_cast<float4*>(h + (size_t)n * HID);
#pragma unroll
    for (int j = 0; j < 8; j++)
        hv[j] = make_float4(acc[4*j], acc[4*j+1], acc[4*j+2], acc[4*j+3]);

    float al[4][4];
#pragma unroll
    for (int hh = 0; hh < 4; hh++) {
        float s0 = 0.f, s1 = 0.f, s2 = 0.f, s3 = 0.f;
#pragma unroll
        for (int d = 0; d < 8; d++) {
            float v = acc[hh * 8 + d];
            s0 = fmaf(v, satt[0][hh*8+d], s0);
            s1 = fmaf(v, satt[1][hh*8+d], s1);
            s2 = fmaf(v, satt[2][hh*8+d], s2);
            s3 = fmaf(v, satt[3][hh*8+d], s3);
        }
        al[0][hh] = s0; al[1][hh] = s1; al[2][hh] = s2; al[3][hh] = s3;
    }
    if (is_addr) {
        *reinterpret_cast<float4*>(as_at + (size_t)n*4) = make_float4(al[0][0],al[0][1],al[0][2],al[0][3]);
        *reinterpret_cast<float4*>(ad_ta + (size_t)n*4) = make_float4(al[1][0],al[1][1],al[1][2],al[1][3]);
        *reinterpret_cast<float4*>(as_aa + (size_t)n*4) = make_float4(al[2][0],al[2][1],al[2][2],al[2][3]);
        *reinterpret_cast<float4*>(ad_aa + (size_t)n*4) = make_float4(al[3][0],al[3][1],al[3][2],al[3][3]);
    } else {
        *reinterpret_cast<float4*>(ad_at + (size_t)n*4) = make_float4(al[0][0],al[0][1],al[0][2],al[0][3]);
        *reinterpret_cast<float4*>(as_ta + (size_t)n*4) = make_float4(al[1][0],al[1][1],al[1][2],al[1][3]);
    }
}

// ---------------------------------------------------------------------------
// Fused relation gather: warp per dst node; lane = channel.
// col entries broadcast via shuffle; 8-edge unrolled groups for MLP.
// ---------------------------------------------------------------------------
__global__ void gather_fused(const int* __restrict__ rs, const int* __restrict__ col,
                             const float* __restrict__ as_ta, const float* __restrict__ ad_ta,
                             const float* __restrict__ ht,   float* __restrict__ oa1,
                             const float* __restrict__ as_aa, const float* __restrict__ ad_aa,
                             const float* __restrict__ ha,   float* __restrict__ oa2,
                             const float* __restrict__ as_at, const float* __restrict__ ad_at,
                             float* __restrict__ otx, int nwarps)
{
    int w = (blockIdx.x * blockDim.x + threadIdx.x) >> 5;
    if (w >= nwarps) return;
    int lane = threadIdx.x & 31;
    int head = lane >> 3;

    const float *as, *ad, *hs;
    float* out;
    int d;
    if (w < N_ADDR)            { as = as_ta; ad = ad_ta; hs = ht; out = oa1; d = w; }
    else if (w < 2 * N_ADDR)   { as = as_aa; ad = ad_aa; hs = ha; out = oa2; d = w - N_ADDR; }
    else                       { as = as_at; ad = ad_at; hs = ha; out = otx; d = w - 2 * N_ADDR; }

    int start = rs[w];
    int n     = rs[w + 1] - start;
    float adv = ad[(size_t)d * 4 + head];

    float acc = 0.f, ds = 0.f;
    while (n > 0) {
        int take = n < 32 ? n : 32;
        int idx = lane < take ? lane : (take - 1);
        int myc = col[start + idx];
#pragma unroll 1
        for (int j0 = 0; j0 < take; j0 += 8) {
            float bb[8], vv[8];
#pragma unroll
            for (int u = 0; u < 8; u++) {
                int s = __shfl_sync(0xFFFFFFFFu, myc, (j0 + u) & 31);
                if (j0 + u < take) {
                    bb[u] = as[s * 4 + head];
                    vv[u] = hs[(size_t)s * HID + lane];
                } else {
                    bb[u] = -1e30f;
                    vv[u] = 0.f;
                }
            }
#pragma unroll
            for (int u = 0; u < 8; u++) {
                float wgt = __expf(fminf(leaky(bb[u] + adv), 70.f));
                acc = fmaf(vv[u], wgt, acc);
                ds += wgt;
            }
        }
        start += take;
        n -= take;
    }
    out[(size_t)d * HID + lane] = acc / (ds + 1e-16f);
}

// ---------------------------------------------------------------------------
// Semantic attention: per-block partials (no global atomics)
// ---------------------------------------------------------------------------
__global__ void sem_mean_kernel(const float* __restrict__ o1, const float* __restrict__ o2,
                                const float* __restrict__ kW, const float* __restrict__ kb,
                                float* __restrict__ parts, int N)
{
    __shared__ float sW[HID * HID];
    __shared__ float sb[HID];
    __shared__ float sacc[64];
    int tid = threadIdx.x;
    for (int i = tid; i < HID * HID; i += blockDim.x) sW[i] = kW[i];
    if (tid < HID) sb[tid] = kb[tid];
    if (tid < 64) sacc[tid] = 0.f;
    __syncthreads();

    int n = blockIdx.x * blockDim.x + tid;
    bool valid = (n < N);
#pragma unroll
    for (int r = 0; r < 2; r++) {
        const float* o = (r == 0) ? o1 : o2;
        float row[HID];
        if (valid) {
            const float4* rv = reinterpret_cast<const float4*>(o + (size_t)n * HID);
#pragma unroll
            for (int j = 0; j < 8; j++) {
                float4 v = rv[j];
                row[4*j+0] = fmaxf(v.x, 0.f); row[4*j+1] = fmaxf(v.y, 0.f);
                row[4*j+2] = fmaxf(v.z, 0.f); row[4*j+3] = fmaxf(v.w, 0.f);
            }
        } else {
#pragma unroll
            for (int j = 0; j < HID; j++) row[j] = 0.f;
        }
#pragma unroll
        for (int c = 0; c < HID; c++) {
            float acc = sb[c];
#pragma unroll
            for (int k = 0; k < HID; k++) acc = fmaf(row[k], sW[k * HID + c], acc);
            float v = valid ? tanh_approx(acc) : 0.f;
#pragma unroll
            for (int off = 16; off > 0; off >>= 1)
                v += __shfl_down_sync(0xFFFFFFFFu, v, off);
            if ((tid & 31) == 0) atomicAdd(&sacc[r * HID + c], v);
        }
    }
    __syncthreads();
    if (tid < 64) parts[blockIdx.x * 64 + tid] = sacc[tid];
}

__global__ void attn_kernel(const float* __restrict__ parts, int nblocks,
                            const float* __restrict__ q, float* __restrict__ attn, float invN)
{
    __shared__ float red[512 + 2];
    int tid = threadIdx.x;          // 512 threads: 8 slices x 64 cols
    int c = tid & 63;
    int slice = tid >> 6;
    float acc = 0.f;
    for (int j = slice; j < nblocks; j += 8) acc += parts[j * 64 + c];
    red[tid] = acc;
    __syncthreads();
    if (tid < 256) red[tid] += red[tid + 256];
    __syncthreads();
    if (tid < 128) red[tid] += red[tid + 128];
    __syncthreads();
    if (tid < 64) {
        float v = (red[tid] + red[tid + 64]) * invN * q[c & 31];
#pragma unroll
        for (int off = 16; off > 0; off >>= 1)
            v += __shfl_down_sync(0xFFFFFFFFu, v, off);
        if ((tid & 31) == 0) red[512 + (tid >> 5)] = v;
    }
    __syncthreads();
    if (tid == 0) {
        float s0 = red[512], s1 = red[513];
        float m = fmaxf(s0, s1);
        float e0 = __expf(s0 - m), e1 = __expf(s1 - m);
        float inv = 1.f / (e0 + e1);
        attn[0] = e0 * inv; attn[1] = e1 * inv;
    }
}

__global__ void combine_final_kernel(const float* __restrict__ o1, const float* __restrict__ o2,
                                     const float* __restrict__ attn,
                                     const float* __restrict__ linW, const float* __restrict__ linb,
                                     float* __restrict__ out, int N)
{
    __shared__ float sw[64];
    __shared__ float sb2[2];
    int tid = threadIdx.x;
    if (tid < 64) sw[tid] = linW[tid];
    if (tid < 2)  sb2[tid] = linb[tid];
    __syncthreads();
    int n = blockIdx.x * blockDim.x + tid;
    if (n >= N) return;
    float a0 = attn[0], a1 = attn[1];
    float s0 = sb2[0], s1 = sb2[1];
    const float4* r1 = reinterpret_cast<const float4*>(o1 + (size_t)n * HID);
    const float4* r2 = reinterpret_cast<const float4*>(o2 + (size_t)n * HID);
#pragma unroll
    for (int j = 0; j < 8; j++) {
        float4 v1 = r1[j], v2 = r2[j];
        float c;
        c = a0*fmaxf(v1.x,0.f) + a1*fmaxf(v2.x,0.f); s0 = fmaf(c, sw[(4*j+0)*2+0], s0); s1 = fmaf(c, sw[(4*j+0)*2+1], s1);
        c = a0*fmaxf(v1.y,0.f) + a1*fmaxf(v2.y,0.f); s0 = fmaf(c, sw[(4*j+1)*2+0], s0); s1 = fmaf(c, sw[(4*j+1)*2+1], s1);
        c = a0*fmaxf(v1.z,0.f) + a1*fmaxf(v2.z,0.f); s0 = fmaf(c, sw[(4*j+2)*2+0], s0); s1 = fmaf(c, sw[(4*j+2)*2+1], s1);
        c = a0*fmaxf(v1.w,0.f) + a1*fmaxf(v2.w,0.f); s0 = fmaf(c, sw[(4*j+3)*2+0], s0); s1 = fmaf(c, sw[(4*j+3)*2+1], s1);
    }
    out[n * 2 + 0] = s0;
    out[n * 2 + 1] = s1;
}

// ---------------------------------------------------------------------------
// Host orchestration
// ---------------------------------------------------------------------------
static void launch_layer(int layer1,
                         const float* xa, const float* xt_or_otx,
                         const float* Wa, const float* ba, const float* Wt, const float* bt,
                         const float* attS, const float* attD,
                         const float* kW, const float* kb, const float* qv,
                         Scratch* S, bool with_tx,
                         const float* linW, const float* linb, float* out)
{
    int nba = (N_ADDR + TB - 1) / TB;
    int nbt = (N_TX   + TB - 1) / TB;

    proj_fused<<<nba + nbt, TB>>>(layer1, nba,
        xa, xt_or_otx, S->oa1, S->oa2, S->attn,
        Wa, ba, Wt, bt, S->ha, S->ht, attS, attD,
        S->as_at, S->ad_ta, S->as_aa, S->ad_aa, S->ad_at, S->as_ta);

    int nwarps = with_tx ? NDST : 2 * N_ADDR;
    int gblocks = (nwarps * 32 + TB - 1) / TB;
    gather_fused<<<gblocks, TB>>>(S->rs, S->col,
        S->as_ta, S->ad_ta, S->ht, S->oa1,
        S->as_aa, S->ad_aa, S->ha, S->oa2,
        S->as_at, S->ad_at, S->otx, nwarps);

    sem_mean_kernel<<<nba, TB>>>(S->oa1, S->oa2, kW, kb, S->sem_parts, N_ADDR);
    attn_kernel<<<1, 512>>>(S->sem_parts, nba, qv, S->attn, 1.f / (float)N_ADDR);

    if (out)
        combine_final_kernel<<<nba, TB>>>(S->oa1, S->oa2, S->attn, linW, linb, out, N_ADDR);
}

extern "C" void kernel_launch(void* const* d_in, const int* in_sizes, int n_in,
                              void* d_out, int out_size)
{
    const float* x_addr  = (const float*)d_in[0];
    const float* x_tx    = (const float*)d_in[1];
    const int*   eat_s   = (const int*)d_in[2];
    const int*   eat_d   = (const int*)d_in[3];
    const int*   eta_s   = (const int*)d_in[4];
    const int*   eta_d   = (const int*)d_in[5];
    const int*   eaa_s   = (const int*)d_in[6];
    const int*   eaa_d   = (const int*)d_in[7];
    const float* pW1     = (const float*)d_in[8];
    const float* pb1     = (const float*)d_in[9];
    const float* pW23    = (const float*)d_in[10];
    const float* pb23    = (const float*)d_in[11];
    const float* att_src = (const float*)d_in[12];
    const float* att_dst = (const float*)d_in[13];
    const float* kW      = (const float*)d_in[14];
    const float* kb      = (const float*)d_in[15];
    const float* q       = (const float*)d_in[16];
    const float* linW    = (const float*)d_in[17];
    const float* linb    = (const float*)d_in[18];
    float* out = (float*)d_out;

    Scratch* S = nullptr;
    cudaGetSymbolAddress((void**)&S, g_scr);

    // ---- Concatenated CSR build (5 launches) ----
    cudaMemsetAsync(S->cnt, 0, sizeof(int) * NDST);
    hist_fused<<<(E_TOT + TB - 1) / TB, TB>>>(eta_d, eaa_d, eat_d, S->cnt);
    int nb = (NDST + SCAN_T - 1) / SCAN_T;   // 489
    scan_local<<<nb, SCAN_T>>>(S->cnt, S->rs, S->bsums, NDST);
    scan_offset<<<nb, SCAN_T>>>(S->rs, S->rs_cur, S->bsums, NDST, E_TOT);
    fill_fused<<<(E_TOT + TB - 1) / TB, TB>>>(eta_s, eta_d, eaa_s, eaa_d, eat_s, eat_d,
                                              S->rs_cur, S->col);

    // ---- Layer 1 (Fin=64, raw inputs) ----
    launch_layer(1, x_addr, x_tx,
                 pW1 + 0, pb1 + 0, pW1 + 64 * 32, pb1 + 32,
                 att_src + 0,  att_dst + 0,
                 kW + 0, kb + 0, q + 0,
                 S, true, nullptr, nullptr, nullptr);

    // ---- Layer 2 (addr = combine(oa1,oa2,attn), tx = relu(otx)) ----
    launch_layer(0, nullptr, S->otx,
                 pW23 + 0 * 1024, pb23 + 0, pW23 + 1 * 1024, pb23 + 32,
                 att_src + 96, att_dst + 96,
                 kW + 1024, kb + 32, q + 32,
                 S, true, nullptr, nullptr, nullptr);

    // ---- Layer 3 (tx dead: skip at relation; fuse final linear) ----
    launch_layer(0, nullptr, S->otx,
                 pW23 + 2 * 1024, pb23 + 64, pW23 + 3 * 1024, pb23 + 96,
                 att_src + 192, att_dst + 192,
                 kW + 2048, kb + 64, q + 64,
                 S, false, linW, linb, out);

    (void)in_sizes; (void)n_in; (void)out_size;
}

// round 11
// speedup vs baseline: 1.0016x; 1.0016x over previous
#include <cuda_runtime.h>
#include <math.h>

#define N_ADDR 150000
#define N_TX   200000
#define HID    32
#define E_TA   1000000
#define E_AA   500000
#define E_AT   1000000
#define E_TOT  2500000
#define NDST   500000      // concatenated dst space: [ta addr | aa addr | at tx]
#define SLOPE  0.2f
#define TB     256
#define SCAN_T 1024

// ---------------------------------------------------------------------------
// Scratch (device global — no runtime allocation)
// ---------------------------------------------------------------------------
struct __align__(128) Scratch {
    float ha [N_ADDR * HID];
    float ht [N_TX   * HID];
    float otx[N_TX   * HID];
    float oa1[N_ADDR * HID];
    float oa2[N_ADDR * HID];
    float as_at[N_ADDR * 4];
    float ad_at[N_TX   * 4];
    float as_ta[N_TX   * 4];
    float ad_ta[N_ADDR * 4];
    float as_aa[N_ADDR * 4];
    float ad_aa[N_ADDR * 4];
    float sem_parts[1024 * 64];
    float attn[2];
    int cnt[NDST];
    int rs [NDST + 1];
    int rs_cur[NDST];
    int col[E_TOT];
    int bsums[512];
};
__device__ Scratch g_scr;

__device__ __forceinline__ float leaky(float v) { return v >= 0.f ? v : SLOPE * v; }
__device__ __forceinline__ float tanh_approx(float x) {
    float r; asm("tanh.approx.f32 %0, %1;" : "=f"(r) : "f"(x)); return r;
}

// ---------------------------------------------------------------------------
// CSR build — concatenated over all 3 relations.
// edge order: [ta (1M) | aa (0.5M) | at (1M)]
// dst space:  [ta addr (150K) | aa addr (150K) | at tx (200K)]
// ---------------------------------------------------------------------------
__global__ void hist_fused(const int* __restrict__ ta_d, const int* __restrict__ aa_d,
                           const int* __restrict__ at_d, int* __restrict__ cnt)
{
    int e = blockIdx.x * blockDim.x + threadIdx.x;
    if (e >= E_TOT) return;
    int g;
    if (e < E_TA)             g = ta_d[e];
    else if (e < E_TA + E_AA) g = N_ADDR + aa_d[e - E_TA];
    else                      g = 2 * N_ADDR + at_d[e - E_TA - E_AA];
    atomicAdd(&cnt[g], 1);
}

// block-local exclusive scan + block sums
__global__ void scan_local(const int* __restrict__ cnt, int* __restrict__ rs,
                           int* __restrict__ bsums, int n)
{
    __shared__ int sd[SCAN_T];
    int tid = threadIdx.x;
    int i = blockIdx.x * SCAN_T + tid;
    int v = (i < n) ? cnt[i] : 0;
    sd[tid] = v;
    __syncthreads();
#pragma unroll
    for (int off = 1; off < SCAN_T; off <<= 1) {
        int t = (tid >= off) ? sd[tid - off] : 0;
        __syncthreads();
        sd[tid] += t;
        __syncthreads();
    }
    if (i < n) rs[i] = sd[tid] - v;
    if (tid == SCAN_T - 1) bsums[blockIdx.x] = sd[tid];
}

// add cross-block offsets; seed rs_cur; write sentinel
__global__ void scan_offset(int* __restrict__ rs, int* __restrict__ rs_cur,
                            const int* __restrict__ bsums, int n, int etot)
{
    __shared__ int sb[SCAN_T];
    int tid = threadIdx.x;
    int bid = blockIdx.x;
    int acc = 0;
    for (int j = tid; j < bid; j += SCAN_T) acc += bsums[j];
    sb[tid] = acc;
    __syncthreads();
#pragma unroll
    for (int off = SCAN_T / 2; off > 0; off >>= 1) {
        if (tid < off) sb[tid] += sb[tid + off];
        __syncthreads();
    }
    int offset = sb[0];
    int i = bid * SCAN_T + tid;
    if (i < n) {
        int r = rs[i] + offset;
        rs[i] = r;
        rs_cur[i] = r;
    }
    if (bid == 0 && tid == 0) rs[n] = etot;
}

__global__ void fill_fused(const int* __restrict__ ta_s, const int* __restrict__ ta_d,
                           const int* __restrict__ aa_s, const int* __restrict__ aa_d,
                           const int* __restrict__ at_s, const int* __restrict__ at_d,
                           int* __restrict__ rs_cur, int* __restrict__ col)
{
    int e = blockIdx.x * blockDim.x + threadIdx.x;
    if (e >= E_TOT) return;
    int g, s;
    if (e < E_TA)              { g = ta_d[e];                          s = ta_s[e]; }
    else if (e < E_TA + E_AA)  { g = N_ADDR + aa_d[e - E_TA];          s = aa_s[e - E_TA]; }
    else                       { g = 2*N_ADDR + at_d[e - E_TA - E_AA]; s = at_s[e - E_TA - E_AA]; }
    int pos = atomicAdd(&rs_cur[g], 1);
    col[pos] = s;
}

// ---------------------------------------------------------------------------
// Fused projection for both node types; L2/L3 addr path consumes the semantic
// combine on the fly. Blocks [0,nba) -> addr; [nba, nba+nbt) -> tx.
// ---------------------------------------------------------------------------
__global__ void proj_fused(int layer1, int nba_blocks,
                           const float* __restrict__ xa,
                           const float* __restrict__ xt,
                           const float* __restrict__ o1, const float* __restrict__ o2,
                           const float* __restrict__ attn,
                           const float* __restrict__ Wa, const float* __restrict__ ba,
                           const float* __restrict__ Wt, const float* __restrict__ bt,
                           float* __restrict__ ha, float* __restrict__ ht,
                           const float* __restrict__ attS, const float* __restrict__ attD,
                           float* __restrict__ as_at, float* __restrict__ ad_ta,
                           float* __restrict__ as_aa, float* __restrict__ ad_aa,
                           float* __restrict__ ad_at, float* __restrict__ as_ta)
{
    __shared__ float sW[64 * HID];
    __shared__ float sb[HID];
    __shared__ float satt[4][HID];
    int tid = threadIdx.x;
    bool is_addr = (blockIdx.x < (unsigned)nba_blocks);
    const float* W = is_addr ? Wa : Wt;
    const float* b = is_addr ? ba : bt;
    int Fin = layer1 ? 64 : 32;
    for (int i = tid; i < Fin * HID; i += blockDim.x) sW[i] = W[i];
    if (tid < HID) {
        sb[tid] = b[tid];
        if (is_addr) {
            satt[0][tid] = attS[tid];            // att_src[at]
            satt[1][tid] = attD[32 + tid];       // att_dst[ta]
            satt[2][tid] = attS[64 + tid];       // att_src[aa]
            satt[3][tid] = attD[64 + tid];       // att_dst[aa]
        } else {
            satt[0][tid] = attD[tid];            // att_dst[at]
            satt[1][tid] = attS[32 + tid];       // att_src[ta]
            satt[2][tid] = 0.f;
            satt[3][tid] = 0.f;
        }
    }
    __syncthreads();

    int blk = is_addr ? blockIdx.x : (blockIdx.x - nba_blocks);
    int N   = is_addr ? N_ADDR : N_TX;
    int n   = blk * blockDim.x + tid;
    if (n >= N) return;

    float acc[HID];
#pragma unroll
    for (int c = 0; c < HID; c++) acc[c] = sb[c];

    if (is_addr && !layer1) {
        float a0 = attn[0], a1 = attn[1];
        const float4* r1 = reinterpret_cast<const float4*>(o1 + (size_t)n * HID);
        const float4* r2 = reinterpret_cast<const float4*>(o2 + (size_t)n * HID);
#pragma unroll
        for (int k4 = 0; k4 < 8; k4++) {
            float4 u1 = r1[k4], u2 = r2[k4];
            float x0 = a0 * fmaxf(u1.x, 0.f) + a1 * fmaxf(u2.x, 0.f);
            float x1 = a0 * fmaxf(u1.y, 0.f) + a1 * fmaxf(u2.y, 0.f);
            float x2 = a0 * fmaxf(u1.z, 0.f) + a1 * fmaxf(u2.z, 0.f);
            float x3 = a0 * fmaxf(u1.w, 0.f) + a1 * fmaxf(u2.w, 0.f);
#pragma unroll
            for (int c = 0; c < HID; c++) {
                acc[c] = fmaf(x0, sW[(k4*4+0)*HID + c], acc[c]);
                acc[c] = fmaf(x1, sW[(k4*4+1)*HID + c], acc[c]);
                acc[c] = fmaf(x2, sW[(k4*4+2)*HID + c], acc[c]);
                acc[c] = fmaf(x3, sW[(k4*4+3)*HID + c], acc[c]);
            }
        }
    } else {
        const float* xr = is_addr ? (xa + (size_t)n * Fin) : (xt + (size_t)n * Fin);
        const float4* xv4 = reinterpret_cast<const float4*>(xr);
        int nk4 = Fin / 4;
        bool do_relu = (!layer1) && !is_addr;
#pragma unroll 4
        for (int k4 = 0; k4 < nk4; k4++) {
            float4 xv = xv4[k4];
            float x0 = do_relu ? fmaxf(xv.x, 0.f) : xv.x;
            float x1 = do_relu ? fmaxf(xv.y, 0.f) : xv.y;
            float x2 = do_relu ? fmaxf(xv.z, 0.f) : xv.z;
            float x3 = do_relu ? fmaxf(xv.w, 0.f) : xv.w;
#pragma unroll
            for (int c = 0; c < HID; c++) {
                acc[c] = fmaf(x0, sW[(k4*4+0)*HID + c], acc[c]);
                acc[c] = fmaf(x1, sW[(k4*4+1)*HID + c], acc[c]);
                acc[c] = fmaf(x2, sW[(k4*4+2)*HID + c], acc[c]);
                acc[c] = fmaf(x3, sW[(k4*4+3)*HID + c], acc[c]);
            }
        }
    }

    float* h = is_addr ? ha : ht;
    float4* hv = reinterpret_cast<float4*>(h + (size_t)n * HID);
#pragma unroll
    for (int j = 0; j < 8; j++)
        hv[j] = make_float4(acc[4*j], acc[4*j+1], acc[4*j+2], acc[4*j+3]);

    float al[4][4];
#pragma unroll
    for (int hh = 0; hh < 4; hh++) {
        float s0 = 0.f, s1 = 0.f, s2 = 0.f, s3 = 0.f;
#pragma unroll
        for (int d = 0; d < 8; d++) {
            float v = acc[hh * 8 + d];
            s0 = fmaf(v, satt[0][hh*8+d], s0);
            s1 = fmaf(v, satt[1][hh*8+d], s1);
            s2 = fmaf(v, satt[2][hh*8+d], s2);
            s3 = fmaf(v, satt[3][hh*8+d], s3);
        }
        al[0][hh] = s0; al[1][hh] = s1; al[2][hh] = s2; al[3][hh] = s3;
    }
    if (is_addr) {
        *reinterpret_cast<float4*>(as_at + (size_t)n*4) = make_float4(al[0][0],al[0][1],al[0][2],al[0][3]);
        *reinterpret_cast<float4*>(ad_ta + (size_t)n*4) = make_float4(al[1][0],al[1][1],al[1][2],al[1][3]);
        *reinterpret_cast<float4*>(as_aa + (size_t)n*4) = make_float4(al[2][0],al[2][1],al[2][2],al[2][3]);
        *reinterpret_cast<float4*>(ad_aa + (size_t)n*4) = make_float4(al[3][0],al[3][1],al[3][2],al[3][3]);
    } else {
        *reinterpret_cast<float4*>(ad_at + (size_t)n*4) = make_float4(al[0][0],al[0][1],al[0][2],al[0][3]);
        *reinterpret_cast<float4*>(as_ta + (size_t)n*4) = make_float4(al[1][0],al[1][1],al[1][2],al[1][3]);
    }
}

// ---------------------------------------------------------------------------
// Fused relation gather: warp per dst node; lane = channel.
// col entries broadcast via shuffle; 8-edge unrolled groups for MLP.
// ---------------------------------------------------------------------------
__global__ void gather_fused(const int* __restrict__ rs, const int* __restrict__ col,
                             const float* __restrict__ as_ta, const float* __restrict__ ad_ta,
                             const float* __restrict__ ht,   float* __restrict__ oa1,
                             const float* __restrict__ as_aa, const float* __restrict__ ad_aa,
                             const float* __restrict__ ha,   float* __restrict__ oa2,
                             const float* __restrict__ as_at, const float* __restrict__ ad_at,
                             float* __restrict__ otx, int nwarps)
{
    int w = (blockIdx.x * blockDim.x + threadIdx.x) >> 5;
    if (w >= nwarps) return;
    int lane = threadIdx.x & 31;
    int head = lane >> 3;

    const float *as, *ad, *hs;
    float* out;
    int d;
    if (w < N_ADDR)            { as = as_ta; ad = ad_ta; hs = ht; out = oa1; d = w; }
    else if (w < 2 * N_ADDR)   { as = as_aa; ad = ad_aa; hs = ha; out = oa2; d = w - N_ADDR; }
    else                       { as = as_at; ad = ad_at; hs = ha; out = otx; d = w - 2 * N_ADDR; }

    int start = rs[w];
    int n     = rs[w + 1] - start;
    float adv = ad[(size_t)d * 4 + head];

    float acc = 0.f, ds = 0.f;
    while (n > 0) {
        int take = n < 32 ? n : 32;
        int idx = lane < take ? lane : (take - 1);
        int myc = col[start + idx];
#pragma unroll 1
        for (int j0 = 0; j0 < take; j0 += 8) {
            float bb[8], vv[8];
#pragma unroll
            for (int u = 0; u < 8; u++) {
                int s = __shfl_sync(0xFFFFFFFFu, myc, (j0 + u) & 31);
                if (j0 + u < take) {
                    bb[u] = as[s * 4 + head];
                    vv[u] = hs[(size_t)s * HID + lane];
                } else {
                    bb[u] = -1e30f;
                    vv[u] = 0.f;
                }
            }
#pragma unroll
            for (int u = 0; u < 8; u++) {
                float wgt = __expf(fminf(leaky(bb[u] + adv), 70.f));
                acc = fmaf(vv[u], wgt, acc);
                ds += wgt;
            }
        }
        start += take;
        n -= take;
    }
    out[(size_t)d * HID + lane] = acc / (ds + 1e-16f);
}

// ---------------------------------------------------------------------------
// Semantic attention: per-block partials (no global atomics)
// ---------------------------------------------------------------------------
__global__ void sem_mean_kernel(const float* __restrict__ o1, const float* __restrict__ o2,
                                const float* __restrict__ kW, const float* __restrict__ kb,
                                float* __restrict__ parts, int N)
{
    __shared__ float sW[HID * HID];
    __shared__ float sb[HID];
    __shared__ float sacc[64];
    int tid = threadIdx.x;
    for (int i = tid; i < HID * HID; i += blockDim.x) sW[i] = kW[i];
    if (tid < HID) sb[tid] = kb[tid];
    if (tid < 64) sacc[tid] = 0.f;
    __syncthreads();

    int n = blockIdx.x * blockDim.x + tid;
    bool valid = (n < N);
#pragma unroll
    for (int r = 0; r < 2; r++) {
        const float* o = (r == 0) ? o1 : o2;
        float row[HID];
        if (valid) {
            const float4* rv = reinterpret_cast<const float4*>(o + (size_t)n * HID);
#pragma unroll
            for (int j = 0; j < 8; j++) {
                float4 v = rv[j];
                row[4*j+0] = fmaxf(v.x, 0.f); row[4*j+1] = fmaxf(v.y, 0.f);
                row[4*j+2] = fmaxf(v.z, 0.f); row[4*j+3] = fmaxf(v.w, 0.f);
            }
        } else {
#pragma unroll
            for (int j = 0; j < HID; j++) row[j] = 0.f;
        }
#pragma unroll
        for (int c = 0; c < HID; c++) {
            float acc = sb[c];
#pragma unroll
            for (int k = 0; k < HID; k++) acc = fmaf(row[k], sW[k * HID + c], acc);
            float v = valid ? tanh_approx(acc) : 0.f;
#pragma unroll
            for (int off = 16; off > 0; off >>= 1)
                v += __shfl_down_sync(0xFFFFFFFFu, v, off);
            if ((tid & 31) == 0) atomicAdd(&sacc[r * HID + c], v);
        }
    }
    __syncthreads();
    if (tid < 64) parts[blockIdx.x * 64 + tid] = sacc[tid];
}

__global__ void attn_kernel(const float* __restrict__ parts, int nblocks,
                            const float* __restrict__ q, float* __restrict__ attn, float invN)
{
    __shared__ float red[512 + 2];
    int tid = threadIdx.x;          // 512 threads: 8 slices x 64 cols
    int c = tid & 63;
    int slice = tid >> 6;
    float acc = 0.f;
    for (int j = slice; j < nblocks; j += 8) acc += parts[j * 64 + c];
    red[tid] = acc;
    __syncthreads();
    if (tid < 256) red[tid] += red[tid + 256];
    __syncthreads();
    if (tid < 128) red[tid] += red[tid + 128];
    __syncthreads();
    if (tid < 64) {
        float v = (red[tid] + red[tid + 64]) * invN * q[c & 31];
#pragma unroll
        for (int off = 16; off > 0; off >>= 1)
            v += __shfl_down_sync(0xFFFFFFFFu, v, off);
        if ((tid & 31) == 0) red[512 + (tid >> 5)] = v;
    }
    __syncthreads();
    if (tid == 0) {
        float s0 = red[512], s1 = red[513];
        float m = fmaxf(s0, s1);
        float e0 = __expf(s0 - m), e1 = __expf(s1 - m);
        float inv = 1.f / (e0 + e1);
        attn[0] = e0 * inv; attn[1] = e1 * inv;
    }
}

__global__ void combine_final_kernel(const float* __restrict__ o1, const float* __restrict__ o2,
                                     const float* __restrict__ attn,
                                     const float* __restrict__ linW, const float* __restrict__ linb,
                                     float* __restrict__ out, int N)
{
    __shared__ float sw[64];
    __shared__ float sb2[2];
    int tid = threadIdx.x;
    if (tid < 64) sw[tid] = linW[tid];
    if (tid < 2)  sb2[tid] = linb[tid];
    __syncthreads();
    int n = blockIdx.x * blockDim.x + tid;
    if (n >= N) return;
    float a0 = attn[0], a1 = attn[1];
    float s0 = sb2[0], s1 = sb2[1];
    const float4* r1 = reinterpret_cast<const float4*>(o1 + (size_t)n * HID);
    const float4* r2 = reinterpret_cast<const float4*>(o2 + (size_t)n * HID);
#pragma unroll
    for (int j = 0; j < 8; j++) {
        float4 v1 = r1[j], v2 = r2[j];
        float c;
        c = a0*fmaxf(v1.x,0.f) + a1*fmaxf(v2.x,0.f); s0 = fmaf(c, sw[(4*j+0)*2+0], s0); s1 = fmaf(c, sw[(4*j+0)*2+1], s1);
        c = a0*fmaxf(v1.y,0.f) + a1*fmaxf(v2.y,0.f); s0 = fmaf(c, sw[(4*j+1)*2+0], s0); s1 = fmaf(c, sw[(4*j+1)*2+1], s1);
        c = a0*fmaxf(v1.z,0.f) + a1*fmaxf(v2.z,0.f); s0 = fmaf(c, sw[(4*j+2)*2+0], s0); s1 = fmaf(c, sw[(4*j+2)*2+1], s1);
        c = a0*fmaxf(v1.w,0.f) + a1*fmaxf(v2.w,0.f); s0 = fmaf(c, sw[(4*j+3)*2+0], s0); s1 = fmaf(c, sw[(4*j+3)*2+1], s1);
    }
    out[n * 2 + 0] = s0;
    out[n * 2 + 1] = s1;
}

// ---------------------------------------------------------------------------
// Host orchestration
// ---------------------------------------------------------------------------
static void launch_layer(int layer1,
                         const float* xa, const float* xt_or_otx,
                         const float* Wa, const float* ba, const float* Wt, const float* bt,
                         const float* attS, const float* attD,
                         const float* kW, const float* kb, const float* qv,
                         Scratch* S, bool with_tx,
                         const float* linW, const float* linb, float* out)
{
    int nba = (N_ADDR + TB - 1) / TB;
    int nbt = (N_TX   + TB - 1) / TB;

    proj_fused<<<nba + nbt, TB>>>(layer1, nba,
        xa, xt_or_otx, S->oa1, S->oa2, S->attn,
        Wa, ba, Wt, bt, S->ha, S->ht, attS, attD,
        S->as_at, S->ad_ta, S->as_aa, S->ad_aa, S->ad_at, S->as_ta);

    int nwarps = with_tx ? NDST : 2 * N_ADDR;
    int gblocks = (nwarps * 32 + TB - 1) / TB;
    gather_fused<<<gblocks, TB>>>(S->rs, S->col,
        S->as_ta, S->ad_ta, S->ht, S->oa1,
        S->as_aa, S->ad_aa, S->ha, S->oa2,
        S->as_at, S->ad_at, S->otx, nwarps);

    sem_mean_kernel<<<nba, TB>>>(S->oa1, S->oa2, kW, kb, S->sem_parts, N_ADDR);
    attn_kernel<<<1, 512>>>(S->sem_parts, nba, qv, S->attn, 1.f / (float)N_ADDR);

    if (out)
        combine_final_kernel<<<nba, TB>>>(S->oa1, S->oa2, S->attn, linW, linb, out, N_ADDR);
}

extern "C" void kernel_launch(void* const* d_in, const int* in_sizes, int n_in,
                              void* d_out, int out_size)
{
    const float* x_addr  = (const float*)d_in[0];
    const float* x_tx    = (const float*)d_in[1];
    const int*   eat_s   = (const int*)d_in[2];
    const int*   eat_d   = (const int*)d_in[3];
    const int*   eta_s   = (const int*)d_in[4];
    const int*   eta_d   = (const int*)d_in[5];
    const int*   eaa_s   = (const int*)d_in[6];
    const int*   eaa_d   = (const int*)d_in[7];
    const float* pW1     = (const float*)d_in[8];
    const float* pb1     = (const float*)d_in[9];
    const float* pW23    = (const float*)d_in[10];
    const float* pb23    = (const float*)d_in[11];
    const float* att_src = (const float*)d_in[12];
    const float* att_dst = (const float*)d_in[13];
    const float* kW      = (const float*)d_in[14];
    const float* kb      = (const float*)d_in[15];
    const float* q       = (const float*)d_in[16];
    const float* linW    = (const float*)d_in[17];
    const float* linb    = (const float*)d_in[18];
    float* out = (float*)d_out;

    Scratch* S = nullptr;
    cudaGetSymbolAddress((void**)&S, g_scr);

    // ---- Concatenated CSR build (5 launches) ----
    cudaMemsetAsync(S->cnt, 0, sizeof(int) * NDST);
    hist_fused<<<(E_TOT + TB - 1) / TB, TB>>>(eta_d, eaa_d, eat_d, S->cnt);
    int nb = (NDST + SCAN_T - 1) / SCAN_T;   // 489
    scan_local<<<nb, SCAN_T>>>(S->cnt, S->rs, S->bsums, NDST);
    scan_offset<<<nb, SCAN_T>>>(S->rs, S->rs_cur, S->bsums, NDST, E_TOT);
    fill_fused<<<(E_TOT + TB - 1) / TB, TB>>>(eta_s, eta_d, eaa_s, eaa_d, eat_s, eat_d,
                                              S->rs_cur, S->col);

    // ---- Layer 1 (Fin=64, raw inputs) ----
    launch_layer(1, x_addr, x_tx,
                 pW1 + 0, pb1 + 0, pW1 + 64 * 32, pb1 + 32,
                 att_src + 0,  att_dst + 0,
                 kW + 0, kb + 0, q + 0,
                 S, true, nullptr, nullptr, nullptr);

    // ---- Layer 2 (addr = combine(oa1,oa2,attn), tx = relu(otx)) ----
    launch_layer(0, nullptr, S->otx,
                 pW23 + 0 * 1024, pb23 + 0, pW23 + 1 * 1024, pb23 + 32,
                 att_src + 96, att_dst + 96,
                 kW + 1024, kb + 32, q + 32,
                 S, true, nullptr, nullptr, nullptr);

    // ---- Layer 3 (tx dead: skip at relation; fuse final linear) ----
    launch_layer(0, nullptr, S->otx,
                 pW23 + 2 * 1024, pb23 + 64, pW23 + 3 * 1024, pb23 + 96,
                 att_src + 192, att_dst + 192,
                 kW + 2048, kb + 64, q + 64,
                 S, false, linW, linb, out);

    (void)in_sizes; (void)n_in; (void)out_size;
}